// round 7
// baseline (speedup 1.0000x reference)
#include <cuda_runtime.h>
#include <cuda_fp16.h>
#include <math.h>
#include <stdint.h>

#define EMBED 256
#define HEADS 8
#define NQ 4096
#define NSP 16384
#define NPTR 64
#define NSPP 4096
#define NKV 4160
#define SCALE_F 0.1767766952966369f      // 32^-0.5
#define LOG2E_F 1.4426950408889634f
#define QSCALE_F (SCALE_F * LOG2E_F)     // folded into Wq/bq
#define BIAS2_F 2.0f                     // log2(POOL*POOL)
#define MAX2_F 4.0f                      // fixed softmax offset (log2): keeps P in fp16 normal range

// -------- scratch (device globals; no allocation allowed) --------
__device__ __half g_qin[NQ * EMBED];
__device__ __half g_kin[NKV * EMBED];
__device__ __half g_vin[NKV * EMBED];
__device__ __half g_Wq[EMBED * EMBED];
__device__ __half g_Wk[EMBED * EMBED];
__device__ __half g_Wv[EMBED * EMBED];
__device__ __half g_Wo[EMBED * EMBED];
__device__ __half g_qh[NQ * EMBED];
__device__ __half g_kh[NKV * EMBED];
__device__ __half g_vh[NKV * EMBED];

// ---------------- PTX helpers ----------------
static __device__ __forceinline__ uint32_t smem_u32(const void* p) {
    return (uint32_t)__cvta_generic_to_shared(p);
}
static __device__ __forceinline__ void ldsm4(uint32_t addr, uint32_t* r) {
    asm volatile("ldmatrix.sync.aligned.m8n8.x4.shared.b16 {%0,%1,%2,%3}, [%4];"
                 : "=r"(r[0]), "=r"(r[1]), "=r"(r[2]), "=r"(r[3]) : "r"(addr));
}
static __device__ __forceinline__ void ldsm4t(uint32_t addr, uint32_t* r) {
    asm volatile("ldmatrix.sync.aligned.m8n8.x4.trans.shared.b16 {%0,%1,%2,%3}, [%4];"
                 : "=r"(r[0]), "=r"(r[1]), "=r"(r[2]), "=r"(r[3]) : "r"(addr));
}
static __device__ __forceinline__ void mma16816(float* d, const uint32_t* a,
                                                uint32_t b0, uint32_t b1) {
    asm volatile(
        "mma.sync.aligned.m16n8k16.row.col.f32.f16.f16.f32 "
        "{%0,%1,%2,%3}, {%4,%5,%6,%7}, {%8,%9}, {%0,%1,%2,%3};"
        : "+f"(d[0]), "+f"(d[1]), "+f"(d[2]), "+f"(d[3])
        : "r"(a[0]), "r"(a[1]), "r"(a[2]), "r"(a[3]), "r"(b0), "r"(b1));
}
static __device__ __forceinline__ void cp_async16(uint32_t dst, const void* src) {
    asm volatile("cp.async.cg.shared.global [%0], [%1], 16;" :: "r"(dst), "l"(src));
}
static __device__ __forceinline__ void cp_commit() {
    asm volatile("cp.async.commit_group;");
}
template <int N>
static __device__ __forceinline__ void cp_wait() {
    asm volatile("cp.async.wait_group %0;" :: "n"(N));
}
static __device__ __forceinline__ uint32_t ex2h2(float a, float b) {
    __half2 h = __floats2half2_rn(a, b);
    uint32_t u = *reinterpret_cast<uint32_t*>(&h);
    uint32_t r;
    asm("ex2.approx.f16x2 %0, %1;" : "=r"(r) : "r"(u));
    return r;
}
static __device__ __forceinline__ uint32_t pack_h2(float a, float b) {
    __half2 h = __floats2half2_rn(a, b);
    return *reinterpret_cast<uint32_t*>(&h);
}
// swizzled offset (half units) inside an Nrow x 32col fp16 tile (64B rows)
static __device__ __forceinline__ int sw(int r, int ch) {
    return r * 32 + ((ch ^ ((r >> 1) & 3)) << 3);
}

// ============================================================
// Kernel 1: prep — pool k/v to fp16, q to fp16, weights to fp16
// (Wq pre-scaled by SCALE*log2e), init out rows to bo.
// ============================================================
#define PREP_R0 (NKV * 64)
#define PREP_R1 (PREP_R0 + NQ * 64)
#define PREP_WN (EMBED * EMBED / 4)
#define PREP_R2 (PREP_R1 + 4 * PREP_WN)
#define PREP_TOTAL (PREP_R2 + NQ * 64)

static __device__ __forceinline__ uint2 f4_to_h4(float4 f, float s) {
    __half2 h01 = __floats2half2_rn(f.x * s, f.y * s);
    __half2 h23 = __floats2half2_rn(f.z * s, f.w * s);
    uint2 u;
    u.x = *reinterpret_cast<uint32_t*>(&h01);
    u.y = *reinterpret_cast<uint32_t*>(&h23);
    return u;
}

__global__ void prep_kernel(const float4* __restrict__ q,
                            const float4* __restrict__ k,
                            const float4* __restrict__ v,
                            const float4* __restrict__ Wq,
                            const float4* __restrict__ Wk,
                            const float4* __restrict__ Wv,
                            const float4* __restrict__ Wo,
                            const float4* __restrict__ bo,
                            float4* __restrict__ out) {
    int gid = blockIdx.x * blockDim.x + threadIdx.x;
    if (gid >= PREP_TOTAL) return;
    if (gid < PREP_R0) {
        int m  = gid >> 6;
        int c4 = gid & 63;
        float4 ko, vo;
        if (m < NSPP) {
            int f = m >> 10;
            int r = m & 1023;
            int i = r >> 5;
            int j = r & 31;
            int base = f * 4096 + (i * 2) * 64 + j * 2;
            float4 a = k[(base) * 64 + c4];
            float4 b = k[(base + 1) * 64 + c4];
            float4 c = k[(base + 64) * 64 + c4];
            float4 d = k[(base + 65) * 64 + c4];
            ko = make_float4(0.25f * (a.x + b.x + c.x + d.x),
                             0.25f * (a.y + b.y + c.y + d.y),
                             0.25f * (a.z + b.z + c.z + d.z),
                             0.25f * (a.w + b.w + c.w + d.w));
            a = v[(base) * 64 + c4];
            b = v[(base + 1) * 64 + c4];
            c = v[(base + 64) * 64 + c4];
            d = v[(base + 65) * 64 + c4];
            vo = make_float4(0.25f * (a.x + b.x + c.x + d.x),
                             0.25f * (a.y + b.y + c.y + d.y),
                             0.25f * (a.z + b.z + c.z + d.z),
                             0.25f * (a.w + b.w + c.w + d.w));
        } else {
            int src = NSP + (m - NSPP);
            ko = k[src * 64 + c4];
            vo = v[src * 64 + c4];
        }
        reinterpret_cast<uint2*>(g_kin)[gid] = f4_to_h4(ko, 1.0f);
        reinterpret_cast<uint2*>(g_vin)[gid] = f4_to_h4(vo, 1.0f);
    } else if (gid < PREP_R1) {
        int i = gid - PREP_R0;
        reinterpret_cast<uint2*>(g_qin)[i] = f4_to_h4(q[i], 1.0f);
    } else if (gid < PREP_R2) {
        int i = gid - PREP_R1;
        int w = i / PREP_WN;
        int j = i - w * PREP_WN;
        if (w == 0)
            reinterpret_cast<uint2*>(g_Wq)[j] = f4_to_h4(Wq[j], QSCALE_F);
        else if (w == 1)
            reinterpret_cast<uint2*>(g_Wk)[j] = f4_to_h4(Wk[j], 1.0f);
        else if (w == 2)
            reinterpret_cast<uint2*>(g_Wv)[j] = f4_to_h4(Wv[j], 1.0f);
        else
            reinterpret_cast<uint2*>(g_Wo)[j] = f4_to_h4(Wo[j], 1.0f);
    } else {
        int i = gid - PREP_R2;       // out init: out[r][:] = bo
        out[i] = bo[i & 63];
    }
}

// ============================================================
// Kernel 2: fp16 MMA GEMM, 3 fused jobs via blockIdx.z (q/k/v).
// BM=64, BN=32, BK=32, 4 warps, 3-stage cp.async ring.
// ============================================================
struct GemmJobs {
    const __half* A[3];
    const __half* W[3];
    const float*  bias[3];
    float         bscale[3];
    __half*       C[3];
    int           M[3];
};

__global__ __launch_bounds__(128) void gemm16_kernel(GemmJobs jobs) {
    __shared__ __half As[3][64 * 40];
    __shared__ __half Ws[3][32 * 40];

    int z = blockIdx.z;
    const __half* A = jobs.A[z];
    const __half* W = jobs.W[z];
    const float* bias = jobs.bias[z];
    float bscale = jobs.bscale[z];
    __half* Cout = jobs.C[z];
    int M = jobs.M[z];

    int tid  = threadIdx.x;
    int warp = tid >> 5;
    int lane = tid & 31;
    int m0 = blockIdx.x * 64;
    int n0 = blockIdx.y * 32;
    if (m0 >= M) return;

    float acc[4][4];
#pragma unroll
    for (int nb = 0; nb < 4; nb++)
#pragma unroll
        for (int i = 0; i < 4; i++) acc[nb][i] = 0.f;

    auto load_chunk = [&](int c, int b) {
        int k0 = c * 32;
#pragma unroll
        for (int i = 0; i < 2; i++) {
            int f = tid + i * 128;
            int row = f >> 2, ch = f & 3;
            cp_async16(smem_u32(&As[b][row * 40 + ch * 8]),
                       &A[(m0 + row) * 256 + k0 + ch * 8]);
        }
        {
            int row = tid >> 2, ch = tid & 3;
            cp_async16(smem_u32(&Ws[b][row * 40 + ch * 8]),
                       &W[(k0 + row) * 256 + n0 + ch * 8]);
        }
        cp_commit();
    };

    auto compute = [&](int buf) {
#pragma unroll
        for (int kb = 0; kb < 2; kb++) {
            uint32_t af[4];
            ldsm4(smem_u32(&As[buf][(warp * 16 + (lane & 15)) * 40 +
                                    kb * 16 + (lane >> 4) * 8]), af);
            uint32_t bf[4];
            ldsm4t(smem_u32(&Ws[buf][(kb * 16 + (lane & 15)) * 40 +
                                     (lane >> 4) * 8]), bf);
            mma16816(acc[0], af, bf[0], bf[1]);
            mma16816(acc[1], af, bf[2], bf[3]);
            uint32_t bf2[4];
            ldsm4t(smem_u32(&Ws[buf][(kb * 16 + (lane & 15)) * 40 +
                                     16 + (lane >> 4) * 8]), bf2);
            mma16816(acc[2], af, bf2[0], bf2[1]);
            mma16816(acc[3], af, bf2[2], bf2[3]);
        }
    };

    load_chunk(0, 0);
    load_chunk(1, 1);

    for (int c = 0; c < 7; c++) {
        cp_wait<1>();
        __syncthreads();
        if (c + 2 < 8) load_chunk(c + 2, (c + 2) % 3);
        compute(c % 3);
    }
    cp_wait<0>();
    __syncthreads();
    compute(7 % 3);

    int r0 = m0 + warp * 16 + (lane >> 2);
    int r1 = r0 + 8;
#pragma unroll
    for (int nb = 0; nb < 4; nb++) {
        int col = n0 + nb * 8 + (lane & 3) * 2;
        float b0 = bias[col] * bscale;
        float b1 = bias[col + 1] * bscale;
        *reinterpret_cast<__half2*>(&Cout[r0 * 256 + col]) =
            __floats2half2_rn(acc[nb][0] + b0, acc[nb][1] + b1);
        *reinterpret_cast<__half2*>(&Cout[r1 * 256 + col]) =
            __floats2half2_rn(acc[nb][2] + b0, acc[nb][3] + b1);
    }
}

// ============================================================
// Kernel 3: flash attention + fused Wo projection.
// fp16 MMA, fixed-offset base-2 softmax (P = exp2(s - C)).
// BM=64 (4 warps, 128 thr), 64-key tiles, 3-stage ring (24KB).
// Epilogue: O-fragments repacked as A-operands, multiplied by the
// head's 32x256 Wo slice (staged in the freed ring), atomicAdd
// into out (pre-initialized to bo by prep).
// grid (64 qtiles, 8 heads) = 512 CTAs.
// ============================================================
#define WOS_STRIDE 264   // 32x256 Wo slice, padded rows (528B: conflict-free ldsm)

__global__ __launch_bounds__(128, 5) void attn_kernel(
        const __half* __restrict__ Q, const __half* __restrict__ K,
        const __half* __restrict__ V, const __half* __restrict__ Wo,
        float* __restrict__ out) {
    __shared__ __half ring[3 * 2 * 2048];   // [stage][K/V][64x32] = 24 KB

    int tid  = threadIdx.x;
    int warp = tid >> 5;
    int lane = tid & 31;
    int h    = blockIdx.y;
    int q0   = blockIdx.x * 64;

    __half* Kst[3] = { ring, ring + 4096, ring + 8192 };
    __half* Vst[3] = { ring + 2048, ring + 6144, ring + 10240 };

    // stage Q through ring[0], extract A-fragments
#pragma unroll
    for (int i = 0; i < 2; i++) {
        int f = tid + i * 128;          // 256 uint4
        int row = f >> 2, ch = f & 3;
        *reinterpret_cast<uint4*>(&Kst[0][sw(row, ch)]) =
            *reinterpret_cast<const uint4*>(&Q[(q0 + row) * 256 + h * 32 + ch * 8]);
    }
    __syncthreads();
    uint32_t aq[2][4];
#pragma unroll
    for (int kb = 0; kb < 2; kb++) {
        uint32_t addr = smem_u32(&Kst[0][sw(warp * 16 + (lane & 15),
                                            kb * 2 + (lane >> 4))]);
        ldsm4(addr, aq[kb]);
    }
    __syncthreads();

    auto load_kv = [&](int t, int b) {
        int kv0 = t * 64;
#pragma unroll
        for (int i = 0; i < 2; i++) {
            int f = tid + i * 128;      // 256 uint4 each for K and V
            int row = f >> 2, ch = f & 3;
            cp_async16(smem_u32(&Kst[b][sw(row, ch)]),
                       &K[(kv0 + row) * 256 + h * 32 + ch * 8]);
            cp_async16(smem_u32(&Vst[b][sw(row, ch)]),
                       &V[(kv0 + row) * 256 + h * 32 + ch * 8]);
        }
        cp_commit();
    };

    load_kv(0, 0);
    load_kv(1, 1);

    float o[4][4];
#pragma unroll
    for (int nb = 0; nb < 4; nb++)
#pragma unroll
        for (int i = 0; i < 4; i++) o[nb][i] = 0.f;
    float l0 = 0.f, l1 = 0.f;

    auto attn_tile = [&](const __half* Kt, const __half* Vt, float C) {
        float s[8][4];
#pragma unroll
        for (int j = 0; j < 8; j++) {
            s[j][0] = s[j][1] = s[j][2] = s[j][3] = 0.f;
            uint32_t b[4];
            uint32_t addr = smem_u32(Kt + sw(j * 8 + (lane & 7), lane >> 3));
            ldsm4(addr, b);
            mma16816(s[j], aq[0], b[0], b[1]);
            mma16816(s[j], aq[1], b[2], b[3]);
        }
        float rs0 = 0.f, rs1 = 0.f;
#pragma unroll
        for (int j2 = 0; j2 < 4; j2++) {
            int ja = 2 * j2, jb = 2 * j2 + 1;
            uint32_t pa0 = ex2h2(s[ja][0] - C, s[ja][1] - C);
            uint32_t pb0 = ex2h2(s[ja][2] - C, s[ja][3] - C);
            uint32_t pa1 = ex2h2(s[jb][0] - C, s[jb][1] - C);
            uint32_t pb1 = ex2h2(s[jb][2] - C, s[jb][3] - C);
            float2 fa0 = __half22float2(*reinterpret_cast<__half2*>(&pa0));
            float2 fb0 = __half22float2(*reinterpret_cast<__half2*>(&pb0));
            float2 fa1 = __half22float2(*reinterpret_cast<__half2*>(&pa1));
            float2 fb1 = __half22float2(*reinterpret_cast<__half2*>(&pb1));
            rs0 += fa0.x + fa0.y + fa1.x + fa1.y;
            rs1 += fb0.x + fb0.y + fb1.x + fb1.y;

            uint32_t ap[4] = { pa0, pb0, pa1, pb1 };
            uint32_t bv[4];
            int vrow = 16 * j2 + (lane & 15);
            uint32_t addr = smem_u32(Vt + sw(vrow, (lane >> 4)));
            ldsm4t(addr, bv);
            mma16816(o[0], ap, bv[0], bv[1]);
            mma16816(o[1], ap, bv[2], bv[3]);
            uint32_t addr2 = smem_u32(Vt + sw(vrow, 2 + (lane >> 4)));
            ldsm4t(addr2, bv);
            mma16816(o[2], ap, bv[0], bv[1]);
            mma16816(o[3], ap, bv[2], bv[3]);
        }
        l0 += rs0;
        l1 += rs1;
    };

    // 64 biased tiles of 64 keys: C = MAX2 - BIAS2 = 2
    for (int t = 0; t < 64; t++) {
        cp_wait<1>();
        __syncthreads();
        if (t + 2 < 65) load_kv(t + 2, (t + 2) % 3);
        attn_tile(Kst[t % 3], Vst[t % 3], MAX2_F - BIAS2_F);
    }
    // final tile 64 (pointer tokens): C = MAX2
    cp_wait<0>();
    __syncthreads();
    attn_tile(Kst[64 % 3], Vst[64 % 3], MAX2_F);

    // cross-lane l reduction
    l0 += __shfl_xor_sync(0xffffffffu, l0, 1);
    l0 += __shfl_xor_sync(0xffffffffu, l0, 2);
    l1 += __shfl_xor_sync(0xffffffffu, l1, 1);
    l1 += __shfl_xor_sync(0xffffffffu, l1, 2);
    float inv0 = 1.f / l0;
    float inv1 = 1.f / l1;

    // ---- fused Wo epilogue ----
    __syncthreads();   // everyone done with the ring
    // stage Wo slice [32 k-rows x 256 n-cols] into ring, stride 264
    __half* WoS = ring;
#pragma unroll
    for (int i = 0; i < 8; i++) {
        int f = tid + i * 128;          // 1024 uint4
        int r = f >> 5, c = f & 31;
        *reinterpret_cast<uint4*>(&WoS[r * WOS_STRIDE + c * 8]) =
            *reinterpret_cast<const uint4*>(&Wo[(h * 32 + r) * 256 + c * 8]);
    }
    __syncthreads();

    // repack normalized O into A-fragments (k = head dim, 2 k16-blocks)
    uint32_t ao[2][4];
#pragma unroll
    for (int kb = 0; kb < 2; kb++) {
        int nb0 = 2 * kb, nb1 = 2 * kb + 1;
        ao[kb][0] = pack_h2(o[nb0][0] * inv0, o[nb0][1] * inv0);
        ao[kb][1] = pack_h2(o[nb0][2] * inv1, o[nb0][3] * inv1);
        ao[kb][2] = pack_h2(o[nb1][0] * inv0, o[nb1][1] * inv0);
        ao[kb][3] = pack_h2(o[nb1][2] * inv1, o[nb1][3] * inv1);
    }

    int r0 = q0 + warp * 16 + (lane >> 2);
    int r1 = r0 + 8;
#pragma unroll
    for (int g2 = 0; g2 < 16; g2++) {
        float acc0[4] = {0.f, 0.f, 0.f, 0.f};
        float acc1[4] = {0.f, 0.f, 0.f, 0.f};
#pragma unroll
        for (int kb = 0; kb < 2; kb++) {
            uint32_t bf[4];
            uint32_t addr = smem_u32(&WoS[(kb * 16 + (lane & 15)) * WOS_STRIDE +
                                          g2 * 16 + (lane >> 4) * 8]);
            ldsm4t(addr, bf);
            mma16816(acc0, ao[kb], bf[0], bf[1]);
            mma16816(acc1, ao[kb], bf[2], bf[3]);
        }
        int col = g2 * 16 + (lane & 3) * 2;
        atomicAdd(&out[r0 * 256 + col],     acc0[0]);
        atomicAdd(&out[r0 * 256 + col + 1], acc0[1]);
        atomicAdd(&out[r1 * 256 + col],     acc0[2]);
        atomicAdd(&out[r1 * 256 + col + 1], acc0[3]);
        atomicAdd(&out[r0 * 256 + col + 8], acc1[0]);
        atomicAdd(&out[r0 * 256 + col + 9], acc1[1]);
        atomicAdd(&out[r1 * 256 + col + 8], acc1[2]);
        atomicAdd(&out[r1 * 256 + col + 9], acc1[3]);
    }
}

// ============================================================
// launcher
// ============================================================
extern "C" void kernel_launch(void* const* d_in, const int* in_sizes, int n_in,
                              void* d_out, int out_size) {
    const float* q  = (const float*)d_in[0];
    const float* k  = (const float*)d_in[1];
    const float* v  = (const float*)d_in[2];
    const float* Wq = (const float*)d_in[3];
    const float* bq = (const float*)d_in[4];
    const float* Wk = (const float*)d_in[5];
    const float* bk = (const float*)d_in[6];
    const float* Wv = (const float*)d_in[7];
    const float* bv = (const float*)d_in[8];
    const float* Wo = (const float*)d_in[9];
    const float* bo = (const float*)d_in[10];
    float* out = (float*)d_out;

    __half *qin, *kin, *vin, *wq, *wk, *wv, *wo, *qh, *kh, *vh;
    cudaGetSymbolAddress((void**)&qin, g_qin);
    cudaGetSymbolAddress((void**)&kin, g_kin);
    cudaGetSymbolAddress((void**)&vin, g_vin);
    cudaGetSymbolAddress((void**)&wq,  g_Wq);
    cudaGetSymbolAddress((void**)&wk,  g_Wk);
    cudaGetSymbolAddress((void**)&wv,  g_Wv);
    cudaGetSymbolAddress((void**)&wo,  g_Wo);
    cudaGetSymbolAddress((void**)&qh,  g_qh);
    cudaGetSymbolAddress((void**)&kh,  g_kh);
    cudaGetSymbolAddress((void**)&vh,  g_vh);

    // 1) prep: pool + fp16 conversions + out := bo
    prep_kernel<<<(PREP_TOTAL + 255) / 256, 256>>>(
        (const float4*)q, (const float4*)k, (const float4*)v,
        (const float4*)Wq, (const float4*)Wk, (const float4*)Wv,
        (const float4*)Wo, (const float4*)bo, (float4*)out);

    // 2) q/k/v projections fused (z = job index)
    GemmJobs qkv;
    qkv.A[0] = qin; qkv.W[0] = wq; qkv.bias[0] = bq; qkv.bscale[0] = QSCALE_F;
    qkv.C[0] = qh;  qkv.M[0] = NQ;
    qkv.A[1] = kin; qkv.W[1] = wk; qkv.bias[1] = bk; qkv.bscale[1] = 1.0f;
    qkv.C[1] = kh;  qkv.M[1] = NKV;
    qkv.A[2] = vin; qkv.W[2] = wv; qkv.bias[2] = bv; qkv.bscale[2] = 1.0f;
    qkv.C[2] = vh;  qkv.M[2] = NKV;
    gemm16_kernel<<<dim3(65, 8, 3), 128>>>(qkv);

    // 3) attention + fused Wo projection (atomicAdd into out)
    attn_kernel<<<dim3(64, 8), 128>>>(qh, kh, vh, wo, out);
}

// round 8
// speedup vs baseline: 1.0608x; 1.0608x over previous
#include <cuda_runtime.h>
#include <cuda_fp16.h>
#include <math.h>
#include <stdint.h>

#define EMBED 256
#define HEADS 8
#define NQ 4096
#define NSP 16384
#define NPTR 64
#define NSPP 4096
#define NKV 4160
#define SCALE_F 0.1767766952966369f      // 32^-0.5
#define LOG2E_F 1.4426950408889634f
#define QSCALE_F (SCALE_F * LOG2E_F)     // folded into Wq/bq
#define BIAS2_F 2.0f                     // log2(POOL*POOL)
#define MAX2_F 4.0f                      // fixed softmax offset (log2), fp16-normal-safe

// -------- scratch (device globals; no allocation allowed) --------
__device__ __half g_qin[NQ * EMBED];
__device__ __half g_kin[NKV * EMBED];
__device__ __half g_vin[NKV * EMBED];
__device__ __half g_Wq[EMBED * EMBED];
__device__ __half g_Wk[EMBED * EMBED];
__device__ __half g_Wv[EMBED * EMBED];
__device__ __half g_Wo[EMBED * EMBED];
__device__ __half g_qh[NQ * EMBED];
__device__ __half g_kh[NKV * EMBED];
__device__ __half g_vh[NKV * EMBED];

// ---------------- PTX helpers ----------------
static __device__ __forceinline__ uint32_t smem_u32(const void* p) {
    return (uint32_t)__cvta_generic_to_shared(p);
}
static __device__ __forceinline__ void ldsm4(uint32_t addr, uint32_t* r) {
    asm volatile("ldmatrix.sync.aligned.m8n8.x4.shared.b16 {%0,%1,%2,%3}, [%4];"
                 : "=r"(r[0]), "=r"(r[1]), "=r"(r[2]), "=r"(r[3]) : "r"(addr));
}
static __device__ __forceinline__ void ldsm4t(uint32_t addr, uint32_t* r) {
    asm volatile("ldmatrix.sync.aligned.m8n8.x4.trans.shared.b16 {%0,%1,%2,%3}, [%4];"
                 : "=r"(r[0]), "=r"(r[1]), "=r"(r[2]), "=r"(r[3]) : "r"(addr));
}
static __device__ __forceinline__ void mma16816(float* d, const uint32_t* a,
                                                uint32_t b0, uint32_t b1) {
    asm volatile(
        "mma.sync.aligned.m16n8k16.row.col.f32.f16.f16.f32 "
        "{%0,%1,%2,%3}, {%4,%5,%6,%7}, {%8,%9}, {%0,%1,%2,%3};"
        : "+f"(d[0]), "+f"(d[1]), "+f"(d[2]), "+f"(d[3])
        : "r"(a[0]), "r"(a[1]), "r"(a[2]), "r"(a[3]), "r"(b0), "r"(b1));
}
static __device__ __forceinline__ void cp_async16(uint32_t dst, const void* src) {
    asm volatile("cp.async.cg.shared.global [%0], [%1], 16;" :: "r"(dst), "l"(src));
}
static __device__ __forceinline__ void cp_commit() {
    asm volatile("cp.async.commit_group;");
}
template <int N>
static __device__ __forceinline__ void cp_wait() {
    asm volatile("cp.async.wait_group %0;" :: "n"(N));
}
static __device__ __forceinline__ uint32_t ex2h2(float a, float b) {
    __half2 h = __floats2half2_rn(a, b);
    uint32_t u = *reinterpret_cast<uint32_t*>(&h);
    uint32_t r;
    asm("ex2.approx.f16x2 %0, %1;" : "=r"(r) : "r"(u));
    return r;
}
static __device__ __forceinline__ uint32_t pack_h2(float a, float b) {
    __half2 h = __floats2half2_rn(a, b);
    return *reinterpret_cast<uint32_t*>(&h);
}
// swizzled offset (half units) inside an Nrow x 32col fp16 tile (64B rows)
static __device__ __forceinline__ int sw(int r, int ch) {
    return r * 32 + ((ch ^ ((r >> 1) & 3)) << 3);
}

// ============================================================
// Kernel 1: prep — pool k/v to fp16, q to fp16, weights to fp16
// (Wq pre-scaled by SCALE*log2e), init out rows to bo.
// ============================================================
#define PREP_R0 (NKV * 64)
#define PREP_R1 (PREP_R0 + NQ * 64)
#define PREP_WN (EMBED * EMBED / 4)
#define PREP_R2 (PREP_R1 + 4 * PREP_WN)
#define PREP_TOTAL (PREP_R2 + NQ * 64)

static __device__ __forceinline__ uint2 f4_to_h4(float4 f, float s) {
    __half2 h01 = __floats2half2_rn(f.x * s, f.y * s);
    __half2 h23 = __floats2half2_rn(f.z * s, f.w * s);
    uint2 u;
    u.x = *reinterpret_cast<uint32_t*>(&h01);
    u.y = *reinterpret_cast<uint32_t*>(&h23);
    return u;
}

__global__ void prep_kernel(const float4* __restrict__ q,
                            const float4* __restrict__ k,
                            const float4* __restrict__ v,
                            const float4* __restrict__ Wq,
                            const float4* __restrict__ Wk,
                            const float4* __restrict__ Wv,
                            const float4* __restrict__ Wo,
                            const float4* __restrict__ bo,
                            float4* __restrict__ out) {
    int gid = blockIdx.x * blockDim.x + threadIdx.x;
    if (gid >= PREP_TOTAL) return;
    if (gid < PREP_R0) {
        int m  = gid >> 6;
        int c4 = gid & 63;
        float4 ko, vo;
        if (m < NSPP) {
            int f = m >> 10;
            int r = m & 1023;
            int i = r >> 5;
            int j = r & 31;
            int base = f * 4096 + (i * 2) * 64 + j * 2;
            float4 a = k[(base) * 64 + c4];
            float4 b = k[(base + 1) * 64 + c4];
            float4 c = k[(base + 64) * 64 + c4];
            float4 d = k[(base + 65) * 64 + c4];
            ko = make_float4(0.25f * (a.x + b.x + c.x + d.x),
                             0.25f * (a.y + b.y + c.y + d.y),
                             0.25f * (a.z + b.z + c.z + d.z),
                             0.25f * (a.w + b.w + c.w + d.w));
            a = v[(base) * 64 + c4];
            b = v[(base + 1) * 64 + c4];
            c = v[(base + 64) * 64 + c4];
            d = v[(base + 65) * 64 + c4];
            vo = make_float4(0.25f * (a.x + b.x + c.x + d.x),
                             0.25f * (a.y + b.y + c.y + d.y),
                             0.25f * (a.z + b.z + c.z + d.z),
                             0.25f * (a.w + b.w + c.w + d.w));
        } else {
            int src = NSP + (m - NSPP);
            ko = k[src * 64 + c4];
            vo = v[src * 64 + c4];
        }
        reinterpret_cast<uint2*>(g_kin)[gid] = f4_to_h4(ko, 1.0f);
        reinterpret_cast<uint2*>(g_vin)[gid] = f4_to_h4(vo, 1.0f);
    } else if (gid < PREP_R1) {
        int i = gid - PREP_R0;
        reinterpret_cast<uint2*>(g_qin)[i] = f4_to_h4(q[i], 1.0f);
    } else if (gid < PREP_R2) {
        int i = gid - PREP_R1;
        int w = i / PREP_WN;
        int j = i - w * PREP_WN;
        if (w == 0)
            reinterpret_cast<uint2*>(g_Wq)[j] = f4_to_h4(Wq[j], QSCALE_F);
        else if (w == 1)
            reinterpret_cast<uint2*>(g_Wk)[j] = f4_to_h4(Wk[j], 1.0f);
        else if (w == 2)
            reinterpret_cast<uint2*>(g_Wv)[j] = f4_to_h4(Wv[j], 1.0f);
        else
            reinterpret_cast<uint2*>(g_Wo)[j] = f4_to_h4(Wo[j], 1.0f);
    } else {
        int i = gid - PREP_R2;       // out init: out[r][:] = bo
        out[i] = bo[i & 63];
    }
}

// ============================================================
// Kernel 2: fp16 MMA GEMM, 3 fused jobs via blockIdx.z (q/k/v).
// BM=64, BN=32, BK=32, 4 warps, 3-stage cp.async ring.
// ============================================================
struct GemmJobs {
    const __half* A[3];
    const __half* W[3];
    const float*  bias[3];
    float         bscale[3];
    __half*       C[3];
    int           M[3];
};

__global__ __launch_bounds__(128) void gemm16_kernel(GemmJobs jobs) {
    __shared__ __half As[3][64 * 40];
    __shared__ __half Ws[3][32 * 40];

    int z = blockIdx.z;
    const __half* A = jobs.A[z];
    const __half* W = jobs.W[z];
    const float* bias = jobs.bias[z];
    float bscale = jobs.bscale[z];
    __half* Cout = jobs.C[z];
    int M = jobs.M[z];

    int tid  = threadIdx.x;
    int warp = tid >> 5;
    int lane = tid & 31;
    int m0 = blockIdx.x * 64;
    int n0 = blockIdx.y * 32;
    if (m0 >= M) return;

    float acc[4][4];
#pragma unroll
    for (int nb = 0; nb < 4; nb++)
#pragma unroll
        for (int i = 0; i < 4; i++) acc[nb][i] = 0.f;

    auto load_chunk = [&](int c, int b) {
        int k0 = c * 32;
#pragma unroll
        for (int i = 0; i < 2; i++) {
            int f = tid + i * 128;
            int row = f >> 2, ch = f & 3;
            cp_async16(smem_u32(&As[b][row * 40 + ch * 8]),
                       &A[(m0 + row) * 256 + k0 + ch * 8]);
        }
        {
            int row = tid >> 2, ch = tid & 3;
            cp_async16(smem_u32(&Ws[b][row * 40 + ch * 8]),
                       &W[(k0 + row) * 256 + n0 + ch * 8]);
        }
        cp_commit();
    };

    auto compute = [&](int buf) {
#pragma unroll
        for (int kb = 0; kb < 2; kb++) {
            uint32_t af[4];
            ldsm4(smem_u32(&As[buf][(warp * 16 + (lane & 15)) * 40 +
                                    kb * 16 + (lane >> 4) * 8]), af);
            uint32_t bf[4];
            ldsm4t(smem_u32(&Ws[buf][(kb * 16 + (lane & 15)) * 40 +
                                     (lane >> 4) * 8]), bf);
            mma16816(acc[0], af, bf[0], bf[1]);
            mma16816(acc[1], af, bf[2], bf[3]);
            uint32_t bf2[4];
            ldsm4t(smem_u32(&Ws[buf][(kb * 16 + (lane & 15)) * 40 +
                                     16 + (lane >> 4) * 8]), bf2);
            mma16816(acc[2], af, bf2[0], bf2[1]);
            mma16816(acc[3], af, bf2[2], bf2[3]);
        }
    };

    load_chunk(0, 0);
    load_chunk(1, 1);

    for (int c = 0; c < 7; c++) {
        cp_wait<1>();
        __syncthreads();
        if (c + 2 < 8) load_chunk(c + 2, (c + 2) % 3);
        compute(c % 3);
    }
    cp_wait<0>();
    __syncthreads();
    compute(7 % 3);

    int r0 = m0 + warp * 16 + (lane >> 2);
    int r1 = r0 + 8;
#pragma unroll
    for (int nb = 0; nb < 4; nb++) {
        int col = n0 + nb * 8 + (lane & 3) * 2;
        float b0 = bias[col] * bscale;
        float b1 = bias[col + 1] * bscale;
        *reinterpret_cast<__half2*>(&Cout[r0 * 256 + col]) =
            __floats2half2_rn(acc[nb][0] + b0, acc[nb][1] + b1);
        *reinterpret_cast<__half2*>(&Cout[r1 * 256 + col]) =
            __floats2half2_rn(acc[nb][2] + b0, acc[nb][3] + b1);
    }
}

// ============================================================
// Kernel 3: flash attention + fused Wo projection.
// fp16 MMA, fixed-offset base-2 softmax (P = exp2(s - C)).
// BM=128 (8 warps, 256 thr), 128-key iterations, 3-stage 48KB ring,
// one barrier per iteration, 2 CTAs/SM.
// Epilogue: normalized O repacked to A-frags, multiplied by the head's
// 32x256 Wo slice (staged into the freed ring), fp32 atomicAdd into out
// (pre-initialized to bo by prep).
// grid (32 qtiles, 8 heads) = 256 CTAs.
// ============================================================
#define WOS_STRIDE 264   // 32x256 Wo slice, padded rows (528B)

__global__ __launch_bounds__(256, 2) void attn_kernel(
        const __half* __restrict__ Q, const __half* __restrict__ K,
        const __half* __restrict__ V, const __half* __restrict__ Wo,
        float* __restrict__ out) {
    __shared__ __half Ks[3][128 * 32];   // swizzled, 24KB
    __shared__ __half Vs[3][128 * 32];   // 24KB

    int tid  = threadIdx.x;
    int warp = tid >> 5;
    int lane = tid & 31;
    int h    = blockIdx.y;
    int q0   = blockIdx.x * 128;

    // stage Q through Ks[0], extract A-fragments, then free it for the ring
#pragma unroll
    for (int i = 0; i < 2; i++) {
        int f = tid + i * 256;
        int row = f >> 2, ch = f & 3;
        *reinterpret_cast<uint4*>(&Ks[0][sw(row, ch)]) =
            *reinterpret_cast<const uint4*>(&Q[(q0 + row) * 256 + h * 32 + ch * 8]);
    }
    __syncthreads();
    uint32_t aq[2][4];
#pragma unroll
    for (int kb = 0; kb < 2; kb++) {
        uint32_t addr = smem_u32(&Ks[0][sw(warp * 16 + (lane & 15),
                                           kb * 2 + (lane >> 4))]);
        ldsm4(addr, aq[kb]);
    }
    __syncthreads();

    auto load_kv = [&](int t, int b) {
        int kv0 = t * 128;
        int items = (t == 32) ? 256 : 512;   // final tile: 64 keys only
#pragma unroll
        for (int i = 0; i < 2; i++) {
            int f = tid + i * 256;
            if (f < items) {
                int row = f >> 2, ch = f & 3;
                cp_async16(smem_u32(&Ks[b][sw(row, ch)]),
                           &K[(kv0 + row) * 256 + h * 32 + ch * 8]);
                cp_async16(smem_u32(&Vs[b][sw(row, ch)]),
                           &V[(kv0 + row) * 256 + h * 32 + ch * 8]);
            }
        }
        cp_commit();
    };

    load_kv(0, 0);
    load_kv(1, 1);

    float o[4][4];
#pragma unroll
    for (int nb = 0; nb < 4; nb++)
#pragma unroll
        for (int i = 0; i < 4; i++) o[nb][i] = 0.f;
    float l0 = 0.f, l1 = 0.f;

    auto attn_tile = [&](const __half* Kt, const __half* Vt, int NJ, float C) {
        float s[16][4];
#pragma unroll
        for (int j = 0; j < 16; j++) {
            if (j >= NJ) break;
            s[j][0] = s[j][1] = s[j][2] = s[j][3] = 0.f;
            uint32_t b[4];
            uint32_t addr = smem_u32(Kt + sw(j * 8 + (lane & 7), lane >> 3));
            ldsm4(addr, b);
            mma16816(s[j], aq[0], b[0], b[1]);
            mma16816(s[j], aq[1], b[2], b[3]);
        }
        float rs0 = 0.f, rs1 = 0.f;
#pragma unroll
        for (int j2 = 0; j2 < 8; j2++) {
            if (j2 >= NJ / 2) break;
            int ja = 2 * j2, jb = 2 * j2 + 1;
            uint32_t pa0 = ex2h2(s[ja][0] - C, s[ja][1] - C);
            uint32_t pb0 = ex2h2(s[ja][2] - C, s[ja][3] - C);
            uint32_t pa1 = ex2h2(s[jb][0] - C, s[jb][1] - C);
            uint32_t pb1 = ex2h2(s[jb][2] - C, s[jb][3] - C);
            float2 fa0 = __half22float2(*reinterpret_cast<__half2*>(&pa0));
            float2 fb0 = __half22float2(*reinterpret_cast<__half2*>(&pb0));
            float2 fa1 = __half22float2(*reinterpret_cast<__half2*>(&pa1));
            float2 fb1 = __half22float2(*reinterpret_cast<__half2*>(&pb1));
            rs0 += fa0.x + fa0.y + fa1.x + fa1.y;
            rs1 += fb0.x + fb0.y + fb1.x + fb1.y;

            uint32_t ap[4] = { pa0, pb0, pa1, pb1 };
            uint32_t bv[4];
            int vrow = 16 * j2 + (lane & 15);
            uint32_t addr = smem_u32(Vt + sw(vrow, (lane >> 4)));
            ldsm4t(addr, bv);
            mma16816(o[0], ap, bv[0], bv[1]);
            mma16816(o[1], ap, bv[2], bv[3]);
            uint32_t addr2 = smem_u32(Vt + sw(vrow, 2 + (lane >> 4)));
            ldsm4t(addr2, bv);
            mma16816(o[2], ap, bv[0], bv[1]);
            mma16816(o[3], ap, bv[2], bv[3]);
        }
        l0 += rs0;
        l1 += rs1;
    };

    // 32 iterations of 128 biased keys: C = MAX2 - BIAS2 = 2
    for (int it = 0; it < 32; it++) {
        cp_wait<1>();
        __syncthreads();
        if (it + 2 <= 32) load_kv(it + 2, (it + 2) % 3);
        attn_tile(Ks[it % 3], Vs[it % 3], 16, MAX2_F - BIAS2_F);
    }
    // final 64 pointer keys, unbiased: C = MAX2 (stage 32%3 == 2)
    cp_wait<0>();
    __syncthreads();
    attn_tile(Ks[2], Vs[2], 8, MAX2_F);

    // cross-lane l reduction
    l0 += __shfl_xor_sync(0xffffffffu, l0, 1);
    l0 += __shfl_xor_sync(0xffffffffu, l0, 2);
    l1 += __shfl_xor_sync(0xffffffffu, l1, 1);
    l1 += __shfl_xor_sync(0xffffffffu, l1, 2);
    float inv0 = 1.f / l0;
    float inv1 = 1.f / l1;

    // ---- fused Wo epilogue ----
    __syncthreads();   // ring free
    __half* WoS = &Ks[0][0];   // 32 x 256 slice @ stride 264 = 16.5KB
#pragma unroll
    for (int i = 0; i < 4; i++) {
        int f = tid + i * 256;          // 1024 uint4
        int r = f >> 5, c = f & 31;
        *reinterpret_cast<uint4*>(&WoS[r * WOS_STRIDE + c * 8]) =
            *reinterpret_cast<const uint4*>(&Wo[(h * 32 + r) * 256 + c * 8]);
    }
    __syncthreads();

    // repack normalized O into A-fragments (k = head dim, 2 k16-blocks)
    uint32_t ao[2][4];
#pragma unroll
    for (int kb = 0; kb < 2; kb++) {
        int nb0 = 2 * kb, nb1 = 2 * kb + 1;
        ao[kb][0] = pack_h2(o[nb0][0] * inv0, o[nb0][1] * inv0);
        ao[kb][1] = pack_h2(o[nb0][2] * inv1, o[nb0][3] * inv1);
        ao[kb][2] = pack_h2(o[nb1][0] * inv0, o[nb1][1] * inv0);
        ao[kb][3] = pack_h2(o[nb1][2] * inv1, o[nb1][3] * inv1);
    }

    int r0 = q0 + warp * 16 + (lane >> 2);
    int r1 = r0 + 8;
#pragma unroll
    for (int g2 = 0; g2 < 16; g2++) {
        float acc0[4] = {0.f, 0.f, 0.f, 0.f};
        float acc1[4] = {0.f, 0.f, 0.f, 0.f};
#pragma unroll
        for (int kb = 0; kb < 2; kb++) {
            uint32_t bf[4];
            uint32_t addr = smem_u32(&WoS[(kb * 16 + (lane & 15)) * WOS_STRIDE +
                                          g2 * 16 + (lane >> 4) * 8]);
            ldsm4t(addr, bf);
            mma16816(acc0, ao[kb], bf[0], bf[1]);
            mma16816(acc1, ao[kb], bf[2], bf[3]);
        }
        int col = g2 * 16 + (lane & 3) * 2;
        atomicAdd(&out[r0 * 256 + col],     acc0[0]);
        atomicAdd(&out[r0 * 256 + col + 1], acc0[1]);
        atomicAdd(&out[r1 * 256 + col],     acc0[2]);
        atomicAdd(&out[r1 * 256 + col + 1], acc0[3]);
        atomicAdd(&out[r0 * 256 + col + 8], acc1[0]);
        atomicAdd(&out[r0 * 256 + col + 9], acc1[1]);
        atomicAdd(&out[r1 * 256 + col + 8], acc1[2]);
        atomicAdd(&out[r1 * 256 + col + 9], acc1[3]);
    }
}

// ============================================================
// launcher
// ============================================================
extern "C" void kernel_launch(void* const* d_in, const int* in_sizes, int n_in,
                              void* d_out, int out_size) {
    const float* q  = (const float*)d_in[0];
    const float* k  = (const float*)d_in[1];
    const float* v  = (const float*)d_in[2];
    const float* Wq = (const float*)d_in[3];
    const float* bq = (const float*)d_in[4];
    const float* Wk = (const float*)d_in[5];
    const float* bk = (const float*)d_in[6];
    const float* Wv = (const float*)d_in[7];
    const float* bv = (const float*)d_in[8];
    const float* Wo = (const float*)d_in[9];
    const float* bo = (const float*)d_in[10];
    float* out = (float*)d_out;

    __half *qin, *kin, *vin, *wq, *wk, *wv, *wo, *qh, *kh, *vh;
    cudaGetSymbolAddress((void**)&qin, g_qin);
    cudaGetSymbolAddress((void**)&kin, g_kin);
    cudaGetSymbolAddress((void**)&vin, g_vin);
    cudaGetSymbolAddress((void**)&wq,  g_Wq);
    cudaGetSymbolAddress((void**)&wk,  g_Wk);
    cudaGetSymbolAddress((void**)&wv,  g_Wv);
    cudaGetSymbolAddress((void**)&wo,  g_Wo);
    cudaGetSymbolAddress((void**)&qh,  g_qh);
    cudaGetSymbolAddress((void**)&kh,  g_kh);
    cudaGetSymbolAddress((void**)&vh,  g_vh);

    // 1) prep: pool + fp16 conversions + out := bo
    prep_kernel<<<(PREP_TOTAL + 255) / 256, 256>>>(
        (const float4*)q, (const float4*)k, (const float4*)v,
        (const float4*)Wq, (const float4*)Wk, (const float4*)Wv,
        (const float4*)Wo, (const float4*)bo, (float4*)out);

    // 2) q/k/v projections fused (z = job index)
    GemmJobs qkv;
    qkv.A[0] = qin; qkv.W[0] = wq; qkv.bias[0] = bq; qkv.bscale[0] = QSCALE_F;
    qkv.C[0] = qh;  qkv.M[0] = NQ;
    qkv.A[1] = kin; qkv.W[1] = wk; qkv.bias[1] = bk; qkv.bscale[1] = 1.0f;
    qkv.C[1] = kh;  qkv.M[1] = NKV;
    qkv.A[2] = vin; qkv.W[2] = wv; qkv.bias[2] = bv; qkv.bscale[2] = 1.0f;
    qkv.C[2] = vh;  qkv.M[2] = NKV;
    gemm16_kernel<<<dim3(65, 8, 3), 128>>>(qkv);

    // 3) attention + fused Wo projection (atomicAdd into out)
    attn_kernel<<<dim3(32, 8), 256>>>(qh, kh, vh, wo, out);
}

// round 9
// speedup vs baseline: 1.0624x; 1.0015x over previous
#include <cuda_runtime.h>
#include <cuda_fp16.h>
#include <math.h>
#include <stdint.h>

#define EMBED 256
#define HEADS 8
#define NQ 4096
#define NSP 16384
#define NPTR 64
#define NSPP 4096
#define NKV 4160
#define SCALE_F 0.1767766952966369f      // 32^-0.5
#define LOG2E_F 1.4426950408889634f
#define QSCALE_F (SCALE_F * LOG2E_F)     // folded into Wq/bq
#define BIAS2_F 2.0f                     // log2(POOL*POOL)
#define MAX2_F 4.0f                      // fixed softmax offset (log2), fp16-normal-safe

// -------- scratch (device globals; no allocation allowed) --------
__device__ __half g_qin[NQ * EMBED];
__device__ __half g_kin[NKV * EMBED];
__device__ __half g_vin[NKV * EMBED];
__device__ __half g_Wq[EMBED * EMBED];
__device__ __half g_Wk[EMBED * EMBED];
__device__ __half g_Wv[EMBED * EMBED];
__device__ __half g_Wo[EMBED * EMBED];
__device__ __half g_qh[NQ * EMBED];
__device__ __half g_kh[NKV * EMBED];
__device__ __half g_vh[NKV * EMBED];
__device__ __half g_attn[NQ * EMBED];

// ---------------- PTX helpers ----------------
static __device__ __forceinline__ uint32_t smem_u32(const void* p) {
    return (uint32_t)__cvta_generic_to_shared(p);
}
static __device__ __forceinline__ void ldsm4(uint32_t addr, uint32_t* r) {
    asm volatile("ldmatrix.sync.aligned.m8n8.x4.shared.b16 {%0,%1,%2,%3}, [%4];"
                 : "=r"(r[0]), "=r"(r[1]), "=r"(r[2]), "=r"(r[3]) : "r"(addr));
}
static __device__ __forceinline__ void ldsm4t(uint32_t addr, uint32_t* r) {
    asm volatile("ldmatrix.sync.aligned.m8n8.x4.trans.shared.b16 {%0,%1,%2,%3}, [%4];"
                 : "=r"(r[0]), "=r"(r[1]), "=r"(r[2]), "=r"(r[3]) : "r"(addr));
}
static __device__ __forceinline__ void mma16816(float* d, const uint32_t* a,
                                                uint32_t b0, uint32_t b1) {
    asm volatile(
        "mma.sync.aligned.m16n8k16.row.col.f32.f16.f16.f32 "
        "{%0,%1,%2,%3}, {%4,%5,%6,%7}, {%8,%9}, {%0,%1,%2,%3};"
        : "+f"(d[0]), "+f"(d[1]), "+f"(d[2]), "+f"(d[3])
        : "r"(a[0]), "r"(a[1]), "r"(a[2]), "r"(a[3]), "r"(b0), "r"(b1));
}
static __device__ __forceinline__ void cp_async16(uint32_t dst, const void* src) {
    asm volatile("cp.async.cg.shared.global [%0], [%1], 16;" :: "r"(dst), "l"(src));
}
static __device__ __forceinline__ void cp_commit() {
    asm volatile("cp.async.commit_group;");
}
template <int N>
static __device__ __forceinline__ void cp_wait() {
    asm volatile("cp.async.wait_group %0;" :: "n"(N));
}
static __device__ __forceinline__ uint32_t ex2h2(float a, float b) {
    __half2 h = __floats2half2_rn(a, b);
    uint32_t u = *reinterpret_cast<uint32_t*>(&h);
    uint32_t r;
    asm("ex2.approx.f16x2 %0, %1;" : "=r"(r) : "r"(u));
    return r;
}
// swizzled offset (half units) inside an Nrow x 32col fp16 tile (64B rows)
static __device__ __forceinline__ int sw(int r, int ch) {
    return r * 32 + ((ch ^ ((r >> 1) & 3)) << 3);
}

// ============================================================
// Kernel 1: prep — pool k/v to fp16, convert q to fp16,
// convert weights to fp16 (Wq pre-scaled by SCALE*log2e).
// ============================================================
#define PREP_R0 (NKV * 64)
#define PREP_R1 (PREP_R0 + NQ * 64)
#define PREP_WN (EMBED * EMBED / 4)
#define PREP_TOTAL (PREP_R1 + 4 * PREP_WN)

static __device__ __forceinline__ uint2 f4_to_h4(float4 f, float s) {
    __half2 h01 = __floats2half2_rn(f.x * s, f.y * s);
    __half2 h23 = __floats2half2_rn(f.z * s, f.w * s);
    uint2 u;
    u.x = *reinterpret_cast<uint32_t*>(&h01);
    u.y = *reinterpret_cast<uint32_t*>(&h23);
    return u;
}

__global__ void prep_kernel(const float4* __restrict__ q,
                            const float4* __restrict__ k,
                            const float4* __restrict__ v,
                            const float4* __restrict__ Wq,
                            const float4* __restrict__ Wk,
                            const float4* __restrict__ Wv,
                            const float4* __restrict__ Wo) {
    int gid = blockIdx.x * blockDim.x + threadIdx.x;
    if (gid >= PREP_TOTAL) return;
    if (gid < PREP_R0) {
        int m  = gid >> 6;
        int c4 = gid & 63;
        float4 ko, vo;
        if (m < NSPP) {
            int f = m >> 10;
            int r = m & 1023;
            int i = r >> 5;
            int j = r & 31;
            int base = f * 4096 + (i * 2) * 64 + j * 2;
            float4 a = k[(base) * 64 + c4];
            float4 b = k[(base + 1) * 64 + c4];
            float4 c = k[(base + 64) * 64 + c4];
            float4 d = k[(base + 65) * 64 + c4];
            ko = make_float4(0.25f * (a.x + b.x + c.x + d.x),
                             0.25f * (a.y + b.y + c.y + d.y),
                             0.25f * (a.z + b.z + c.z + d.z),
                             0.25f * (a.w + b.w + c.w + d.w));
            a = v[(base) * 64 + c4];
            b = v[(base + 1) * 64 + c4];
            c = v[(base + 64) * 64 + c4];
            d = v[(base + 65) * 64 + c4];
            vo = make_float4(0.25f * (a.x + b.x + c.x + d.x),
                             0.25f * (a.y + b.y + c.y + d.y),
                             0.25f * (a.z + b.z + c.z + d.z),
                             0.25f * (a.w + b.w + c.w + d.w));
        } else {
            int src = NSP + (m - NSPP);
            ko = k[src * 64 + c4];
            vo = v[src * 64 + c4];
        }
        reinterpret_cast<uint2*>(g_kin)[gid] = f4_to_h4(ko, 1.0f);
        reinterpret_cast<uint2*>(g_vin)[gid] = f4_to_h4(vo, 1.0f);
    } else if (gid < PREP_R1) {
        int i = gid - PREP_R0;
        reinterpret_cast<uint2*>(g_qin)[i] = f4_to_h4(q[i], 1.0f);
    } else {
        int i = gid - PREP_R1;
        int w = i / PREP_WN;
        int j = i - w * PREP_WN;
        if (w == 0)
            reinterpret_cast<uint2*>(g_Wq)[j] = f4_to_h4(Wq[j], QSCALE_F);
        else if (w == 1)
            reinterpret_cast<uint2*>(g_Wk)[j] = f4_to_h4(Wk[j], 1.0f);
        else if (w == 2)
            reinterpret_cast<uint2*>(g_Wv)[j] = f4_to_h4(Wv[j], 1.0f);
        else
            reinterpret_cast<uint2*>(g_Wo)[j] = f4_to_h4(Wo[j], 1.0f);
    }
}

// ============================================================
// Kernel 2: fp16 MMA GEMM, up to 3 fused jobs via blockIdx.z.
// BM=64, BN=32, BK=32, 4 warps, 3-stage cp.async ring.
// ============================================================
struct GemmJobs {
    const __half* A[3];
    const __half* W[3];
    const float*  bias[3];
    float         bscale[3];
    void*         C[3];
    int           M[3];
};

template <bool HALF_OUT>
__global__ __launch_bounds__(128) void gemm16_kernel(GemmJobs jobs) {
    __shared__ __half As[3][64 * 40];
    __shared__ __half Ws[3][32 * 40];

    int z = blockIdx.z;
    const __half* A = jobs.A[z];
    const __half* W = jobs.W[z];
    const float* bias = jobs.bias[z];
    float bscale = jobs.bscale[z];
    void* Cout = jobs.C[z];
    int M = jobs.M[z];

    int tid  = threadIdx.x;
    int warp = tid >> 5;
    int lane = tid & 31;
    int m0 = blockIdx.x * 64;
    int n0 = blockIdx.y * 32;
    if (m0 >= M) return;

    float acc[4][4];
#pragma unroll
    for (int nb = 0; nb < 4; nb++)
#pragma unroll
        for (int i = 0; i < 4; i++) acc[nb][i] = 0.f;

    auto load_chunk = [&](int c, int b) {
        int k0 = c * 32;
#pragma unroll
        for (int i = 0; i < 2; i++) {
            int f = tid + i * 128;
            int row = f >> 2, ch = f & 3;
            cp_async16(smem_u32(&As[b][row * 40 + ch * 8]),
                       &A[(m0 + row) * 256 + k0 + ch * 8]);
        }
        {
            int row = tid >> 2, ch = tid & 3;
            cp_async16(smem_u32(&Ws[b][row * 40 + ch * 8]),
                       &W[(k0 + row) * 256 + n0 + ch * 8]);
        }
        cp_commit();
    };

    auto compute = [&](int buf) {
#pragma unroll
        for (int kb = 0; kb < 2; kb++) {
            uint32_t af[4];
            ldsm4(smem_u32(&As[buf][(warp * 16 + (lane & 15)) * 40 +
                                    kb * 16 + (lane >> 4) * 8]), af);
            uint32_t bf[4];
            ldsm4t(smem_u32(&Ws[buf][(kb * 16 + (lane & 15)) * 40 +
                                     (lane >> 4) * 8]), bf);
            mma16816(acc[0], af, bf[0], bf[1]);
            mma16816(acc[1], af, bf[2], bf[3]);
            uint32_t bf2[4];
            ldsm4t(smem_u32(&Ws[buf][(kb * 16 + (lane & 15)) * 40 +
                                     16 + (lane >> 4) * 8]), bf2);
            mma16816(acc[2], af, bf2[0], bf2[1]);
            mma16816(acc[3], af, bf2[2], bf2[3]);
        }
    };

    load_chunk(0, 0);
    load_chunk(1, 1);

    for (int c = 0; c < 7; c++) {
        cp_wait<1>();
        __syncthreads();
        if (c + 2 < 8) load_chunk(c + 2, (c + 2) % 3);
        compute(c % 3);
    }
    cp_wait<0>();
    __syncthreads();
    compute(7 % 3);

    int r0 = m0 + warp * 16 + (lane >> 2);
    int r1 = r0 + 8;
#pragma unroll
    for (int nb = 0; nb < 4; nb++) {
        int col = n0 + nb * 8 + (lane & 3) * 2;
        float b0 = bias[col] * bscale;
        float b1 = bias[col + 1] * bscale;
        if (HALF_OUT) {
            __half* C = (__half*)Cout;
            *reinterpret_cast<__half2*>(&C[r0 * 256 + col]) =
                __floats2half2_rn(acc[nb][0] + b0, acc[nb][1] + b1);
            *reinterpret_cast<__half2*>(&C[r1 * 256 + col]) =
                __floats2half2_rn(acc[nb][2] + b0, acc[nb][3] + b1);
        } else {
            float* C = (float*)Cout;
            *reinterpret_cast<float2*>(&C[r0 * 256 + col]) =
                make_float2(acc[nb][0] + b0, acc[nb][1] + b1);
            *reinterpret_cast<float2*>(&C[r1 * 256 + col]) =
                make_float2(acc[nb][2] + b0, acc[nb][3] + b1);
        }
    }
}

// ============================================================
// Kernel 3: flash attention, fp16 MMA, fixed-offset base-2 softmax.
// INTERLEAVED per-16-key groups: QK MMA -> exp2 -> PV MMA with only
// 8 live logit registers (no s[16][4] array -> no spills).
// BM=128 (8 warps, 256 thr), 128-key iterations, 3-stage 48KB ring,
// one barrier per iteration, 2 CTAs/SM.
// grid (32 qtiles, 8 heads) = 256 CTAs.
// ============================================================
__global__ __launch_bounds__(256, 2) void attn_kernel(
        const __half* __restrict__ Q, const __half* __restrict__ K,
        const __half* __restrict__ V, __half* __restrict__ O) {
    __shared__ __half Ks[3][128 * 32];   // swizzled, 24KB
    __shared__ __half Vs[3][128 * 32];   // 24KB

    int tid  = threadIdx.x;
    int warp = tid >> 5;
    int lane = tid & 31;
    int h    = blockIdx.y;
    int q0   = blockIdx.x * 128;

    // stage Q through Ks[0], extract A-fragments, then free it for the ring
#pragma unroll
    for (int i = 0; i < 2; i++) {
        int f = tid + i * 256;
        int row = f >> 2, ch = f & 3;
        *reinterpret_cast<uint4*>(&Ks[0][sw(row, ch)]) =
            *reinterpret_cast<const uint4*>(&Q[(q0 + row) * 256 + h * 32 + ch * 8]);
    }
    __syncthreads();
    uint32_t aq[2][4];
#pragma unroll
    for (int kb = 0; kb < 2; kb++) {
        uint32_t addr = smem_u32(&Ks[0][sw(warp * 16 + (lane & 15),
                                           kb * 2 + (lane >> 4))]);
        ldsm4(addr, aq[kb]);
    }
    __syncthreads();

    auto load_kv = [&](int t, int b) {
        int kv0 = t * 128;
        int items = (t == 32) ? 256 : 512;   // final tile: 64 keys only
#pragma unroll
        for (int i = 0; i < 2; i++) {
            int f = tid + i * 256;
            if (f < items) {
                int row = f >> 2, ch = f & 3;
                cp_async16(smem_u32(&Ks[b][sw(row, ch)]),
                           &K[(kv0 + row) * 256 + h * 32 + ch * 8]);
                cp_async16(smem_u32(&Vs[b][sw(row, ch)]),
                           &V[(kv0 + row) * 256 + h * 32 + ch * 8]);
            }
        }
        cp_commit();
    };

    load_kv(0, 0);
    load_kv(1, 1);

    float o[4][4];
#pragma unroll
    for (int nb = 0; nb < 4; nb++)
#pragma unroll
        for (int i = 0; i < 4; i++) o[nb][i] = 0.f;
    float l0 = 0.f, l1 = 0.f;

    // per-lane smem sub-offsets
    int krow = lane & 7, kch = lane >> 3;
    int vrow_b = lane & 15, vch = lane >> 4;

    // One 16-key group: QK (4 HMMA) -> exp2 (4 MUFU) -> PV (4 HMMA).
    // Only 8 logit floats live at any time.
    auto group = [&](const __half* Kt, const __half* Vt, int j2, float C,
                     float& rs0, float& rs1) {
        float s0[4] = {0.f, 0.f, 0.f, 0.f};
        float s1[4] = {0.f, 0.f, 0.f, 0.f};
        uint32_t b[4];
        ldsm4(smem_u32(Kt + sw((2 * j2) * 8 + krow, kch)), b);
        mma16816(s0, aq[0], b[0], b[1]);
        mma16816(s0, aq[1], b[2], b[3]);
        ldsm4(smem_u32(Kt + sw((2 * j2 + 1) * 8 + krow, kch)), b);
        mma16816(s1, aq[0], b[0], b[1]);
        mma16816(s1, aq[1], b[2], b[3]);

        uint32_t ap[4];
        ap[0] = ex2h2(s0[0] - C, s0[1] - C);   // rows r0 (j even block)
        ap[1] = ex2h2(s0[2] - C, s0[3] - C);   // rows r0+8
        ap[2] = ex2h2(s1[0] - C, s1[1] - C);
        ap[3] = ex2h2(s1[2] - C, s1[3] - C);
        float2 f0 = __half22float2(*reinterpret_cast<__half2*>(&ap[0]));
        float2 f1 = __half22float2(*reinterpret_cast<__half2*>(&ap[1]));
        float2 f2 = __half22float2(*reinterpret_cast<__half2*>(&ap[2]));
        float2 f3 = __half22float2(*reinterpret_cast<__half2*>(&ap[3]));
        rs0 += f0.x + f0.y + f2.x + f2.y;
        rs1 += f1.x + f1.y + f3.x + f3.y;

        uint32_t bv[4];
        int vrow = 16 * j2 + vrow_b;
        ldsm4t(smem_u32(Vt + sw(vrow, vch)), bv);
        mma16816(o[0], ap, bv[0], bv[1]);
        mma16816(o[1], ap, bv[2], bv[3]);
        ldsm4t(smem_u32(Vt + sw(vrow, 2 + vch)), bv);
        mma16816(o[2], ap, bv[0], bv[1]);
        mma16816(o[3], ap, bv[2], bv[3]);
    };

    // 32 iterations of 128 biased keys (8 groups): C = MAX2 - BIAS2 = 2
    for (int it = 0; it < 32; it++) {
        cp_wait<1>();
        __syncthreads();
        if (it + 2 <= 32) load_kv(it + 2, (it + 2) % 3);
        const __half* Kt = Ks[it % 3];
        const __half* Vt = Vs[it % 3];
        float rs0 = 0.f, rs1 = 0.f;
#pragma unroll
        for (int j2 = 0; j2 < 8; j2++)
            group(Kt, Vt, j2, MAX2_F - BIAS2_F, rs0, rs1);
        l0 += rs0;
        l1 += rs1;
    }
    // final 64 pointer keys (4 groups), unbiased: C = MAX2 (stage 2)
    cp_wait<0>();
    __syncthreads();
    {
        float rs0 = 0.f, rs1 = 0.f;
#pragma unroll
        for (int j2 = 0; j2 < 4; j2++)
            group(Ks[2], Vs[2], j2, MAX2_F, rs0, rs1);
        l0 += rs0;
        l1 += rs1;
    }

    // cross-lane l reduction (l accumulation is linear; deferred)
    l0 += __shfl_xor_sync(0xffffffffu, l0, 1);
    l0 += __shfl_xor_sync(0xffffffffu, l0, 2);
    l1 += __shfl_xor_sync(0xffffffffu, l1, 1);
    l1 += __shfl_xor_sync(0xffffffffu, l1, 2);

    float inv0 = 1.f / l0;
    float inv1 = 1.f / l1;
    int r0 = q0 + warp * 16 + (lane >> 2);
    int r1 = r0 + 8;
#pragma unroll
    for (int nb = 0; nb < 4; nb++) {
        int col = h * 32 + nb * 8 + (lane & 3) * 2;
        *reinterpret_cast<__half2*>(&O[r0 * 256 + col]) =
            __floats2half2_rn(o[nb][0] * inv0, o[nb][1] * inv0);
        *reinterpret_cast<__half2*>(&O[r1 * 256 + col]) =
            __floats2half2_rn(o[nb][2] * inv1, o[nb][3] * inv1);
    }
}

// ============================================================
// launcher
// ============================================================
extern "C" void kernel_launch(void* const* d_in, const int* in_sizes, int n_in,
                              void* d_out, int out_size) {
    const float* q  = (const float*)d_in[0];
    const float* k  = (const float*)d_in[1];
    const float* v  = (const float*)d_in[2];
    const float* Wq = (const float*)d_in[3];
    const float* bq = (const float*)d_in[4];
    const float* Wk = (const float*)d_in[5];
    const float* bk = (const float*)d_in[6];
    const float* Wv = (const float*)d_in[7];
    const float* bv = (const float*)d_in[8];
    const float* Wo = (const float*)d_in[9];
    const float* bo = (const float*)d_in[10];
    float* out = (float*)d_out;

    __half *qin, *kin, *vin, *wq, *wk, *wv, *wo, *qh, *kh, *vh, *attn;
    cudaGetSymbolAddress((void**)&qin, g_qin);
    cudaGetSymbolAddress((void**)&kin, g_kin);
    cudaGetSymbolAddress((void**)&vin, g_vin);
    cudaGetSymbolAddress((void**)&wq,  g_Wq);
    cudaGetSymbolAddress((void**)&wk,  g_Wk);
    cudaGetSymbolAddress((void**)&wv,  g_Wv);
    cudaGetSymbolAddress((void**)&wo,  g_Wo);
    cudaGetSymbolAddress((void**)&qh,  g_qh);
    cudaGetSymbolAddress((void**)&kh,  g_kh);
    cudaGetSymbolAddress((void**)&vh,  g_vh);
    cudaGetSymbolAddress((void**)&attn, g_attn);

    // 1) prep: pool + fp16 conversions
    prep_kernel<<<(PREP_TOTAL + 255) / 256, 256>>>(
        (const float4*)q, (const float4*)k, (const float4*)v,
        (const float4*)Wq, (const float4*)Wk, (const float4*)Wv, (const float4*)Wo);

    // 2) q/k/v projections fused (z = job index)
    GemmJobs qkv;
    qkv.A[0] = qin; qkv.W[0] = wq; qkv.bias[0] = bq; qkv.bscale[0] = QSCALE_F;
    qkv.C[0] = qh;  qkv.M[0] = NQ;
    qkv.A[1] = kin; qkv.W[1] = wk; qkv.bias[1] = bk; qkv.bscale[1] = 1.0f;
    qkv.C[1] = kh;  qkv.M[1] = NKV;
    qkv.A[2] = vin; qkv.W[2] = wv; qkv.bias[2] = bv; qkv.bscale[2] = 1.0f;
    qkv.C[2] = vh;  qkv.M[2] = NKV;
    gemm16_kernel<true><<<dim3(65, 8, 3), 128>>>(qkv);

    // 3) attention (interleaved, spill-free)
    attn_kernel<<<dim3(32, 8), 256>>>(qh, kh, vh, attn);

    // 4) output projection (fp32 out)
    GemmJobs ojob;
    ojob.A[0] = attn; ojob.W[0] = wo; ojob.bias[0] = bo; ojob.bscale[0] = 1.0f;
    ojob.C[0] = out;  ojob.M[0] = NQ;
    ojob.A[1] = attn; ojob.W[1] = wo; ojob.bias[1] = bo; ojob.bscale[1] = 1.0f;
    ojob.C[1] = out;  ojob.M[1] = NQ;
    ojob.A[2] = attn; ojob.W[2] = wo; ojob.bias[2] = bo; ojob.bscale[2] = 1.0f;
    ojob.C[2] = out;  ojob.M[2] = NQ;
    gemm16_kernel<false><<<dim3(64, 8, 1), 128>>>(ojob);
}